// round 12
// baseline (speedup 1.0000x reference)
#include <cuda_runtime.h>
#include <cuda_bf16.h>
#include <cstdint>

#define CUBE_L   512
#define EQU_H    1024
#define EQU_W    2048
#define E_COUNT  4
#define CHANNELS 3
#define NPLANES  (E_COUNT * CHANNELS)   // 12
#define PLANE    (CUBE_L * CUBE_L)      // 262144
#define NPIX     (EQU_H * EQU_W)        // 2097152

#define TILE_W   32
#define TILE_H   4
#define DEPTH    3                      // planes in flight

// Element offset of plane k's base relative to x + 3f*PLANE.
// k = e*CHANNELS + c  ->  (18e + c) * PLANE. Folds to an immediate when k
// is a compile-time constant (fully unrolled loop).
__device__ __forceinline__ constexpr size_t poff(int k) {
    return (size_t)(18 * (k / CHANNELS) + (k % CHANNELS)) * PLANE;
}

// 1 px/thread, warp = 32 consecutive px along w (max gather coherence),
// 32x4 tiles. Depth-3 plane pipeline with STATIC ring indexing (k % 3 is
// compile-time in the fully unrolled loop): no rotation MOVs.
// 128-thread CTAs, 10 CTAs/SM: 40 warps with fine scheduling granularity.
__global__ __launch_bounds__(TILE_W * TILE_H, 10) void cube2equirec_kernel(
    const float* __restrict__ x,        // (E*6, C, L, L)
    const float* __restrict__ uv,       // (H, W, 2)
    const int*   __restrict__ face_idx, // (H, W)
    float*       __restrict__ out)      // (E, C, H, W)
{
    const int w = blockIdx.x * TILE_W + (threadIdx.x & (TILE_W - 1));
    const int h = blockIdx.y * TILE_H + (threadIdx.x >> 5);
    const int p = h * EQU_W + w;

    const float2 uvp = __ldcs(reinterpret_cast<const float2*>(uv) + p);
    const int f = __ldcs(face_idx + p);

    const float u = uvp.x;
    const float v = uvp.y;

    int x0 = (int)floorf(u);
    int y0 = (int)floorf(v);
    x0 = min(max(x0, 0), CUBE_L - 1);
    y0 = min(max(y0, 0), CUBE_L - 1);
    const int x1 = min(x0 + 1, CUBE_L - 1);
    const int y1 = min(y0 + 1, CUBE_L - 1);

    const float wx = u - (float)x0;
    const float wy = v - (float)y0;
    const float w00 = (1.0f - wx) * (1.0f - wy);
    const float w01 = wx * (1.0f - wy);
    const float w10 = (1.0f - wx) * wy;
    const float w11 = wx * wy;

    const int o00 = y0 * CUBE_L + x0;
    const int o01 = y0 * CUBE_L + x1;
    const int o10 = y1 * CUBE_L + x0;
    const int o11 = y1 * CUBE_L + x1;

    // Plane k = e*CHANNELS + c lives at x + (18e + 3f + c)*PLANE.
    const float* __restrict__ b = x + (size_t)(3 * f) * PLANE;

    // Depth-3 ring of tap sets; ring index is compile-time (loop unrolled).
    float g[DEPTH][4];

    // Prologue: planes 0 and 1 in flight
    #pragma unroll
    for (int k = 0; k < DEPTH - 1; ++k) {
        const float* bk = b + poff(k);
        g[k][0] = __ldg(bk + o00); g[k][1] = __ldg(bk + o01);
        g[k][2] = __ldg(bk + o10); g[k][3] = __ldg(bk + o11);
    }

    #pragma unroll
    for (int k = 0; k < NPLANES; ++k) {
        // Kick off plane k+2 before consuming plane k.
        if (k + DEPTH - 1 < NPLANES) {
            const int kn = k + DEPTH - 1;
            const float* bn = b + poff(kn);
            float* gn = g[kn % DEPTH];
            gn[0] = __ldg(bn + o00); gn[1] = __ldg(bn + o01);
            gn[2] = __ldg(bn + o10); gn[3] = __ldg(bn + o11);
        }
        const float* gk = g[k % DEPTH];
        const float val = gk[0] * w00 + gk[1] * w01 + gk[2] * w10 + gk[3] * w11;
        __stcs(out + (size_t)k * NPIX + p, val);
    }
}

extern "C" void kernel_launch(void* const* d_in, const int* in_sizes, int n_in,
                              void* d_out, int out_size)
{
    const float* x        = (const float*)d_in[0];
    const float* uv       = (const float*)d_in[1];
    const int*   face_idx = (const int*)d_in[2];
    float*       out      = (float*)d_out;

    dim3 block(TILE_W * TILE_H);                      // 128 threads
    dim3 grid(EQU_W / TILE_W, EQU_H / TILE_H);        // 64 x 256 = 16384
    cube2equirec_kernel<<<grid, block>>>(x, uv, face_idx, out);
}

// round 13
// speedup vs baseline: 1.0363x; 1.0363x over previous
#include <cuda_runtime.h>
#include <cuda_bf16.h>
#include <cstdint>

#define CUBE_L   512
#define EQU_H    1024
#define EQU_W    2048
#define E_COUNT  4
#define CHANNELS 3
#define NPLANES  (E_COUNT * CHANNELS)   // 12
#define PLANE    (CUBE_L * CUBE_L)      // 262144
#define NPIX     (EQU_H * EQU_W)        // 2097152

#define TILE_W   32
#define TILE_H   8
#define DEPTH    3                      // planes in flight

// Element offset of plane k's base relative to x + 3f*PLANE.
// k = e*CHANNELS + c  ->  (18e + c) * PLANE. Folds to an immediate when k
// is a compile-time constant (fully unrolled loop).
__device__ __forceinline__ constexpr size_t poff(int k) {
    return (size_t)(18 * (k / CHANNELS) + (k % CHANNELS)) * PLANE;
}

// Proven optimum shape (R10): 1 px/thread, warp = 32 consecutive px along w
// (max gather coherence), 32x8 tiles (best vertical L1 tap reuse), 256-thread
// CTAs at 5 CTAs/SM (40 warps). Depth-3 plane pipeline, now with STATIC ring
// indexing (k % 3 compile-time in the unrolled loop) -> no rotation MOVs.
__global__ __launch_bounds__(TILE_W * TILE_H, 5) void cube2equirec_kernel(
    const float* __restrict__ x,        // (E*6, C, L, L)
    const float* __restrict__ uv,       // (H, W, 2)
    const int*   __restrict__ face_idx, // (H, W)
    float*       __restrict__ out)      // (E, C, H, W)
{
    const int w = blockIdx.x * TILE_W + (threadIdx.x & (TILE_W - 1));
    const int h = blockIdx.y * TILE_H + (threadIdx.x >> 5);
    const int p = h * EQU_W + w;

    const float2 uvp = __ldcs(reinterpret_cast<const float2*>(uv) + p);
    const int f = __ldcs(face_idx + p);

    const float u = uvp.x;
    const float v = uvp.y;

    int x0 = (int)floorf(u);
    int y0 = (int)floorf(v);
    x0 = min(max(x0, 0), CUBE_L - 1);
    y0 = min(max(y0, 0), CUBE_L - 1);
    const int x1 = min(x0 + 1, CUBE_L - 1);
    const int y1 = min(y0 + 1, CUBE_L - 1);

    const float wx = u - (float)x0;
    const float wy = v - (float)y0;
    const float w00 = (1.0f - wx) * (1.0f - wy);
    const float w01 = wx * (1.0f - wy);
    const float w10 = (1.0f - wx) * wy;
    const float w11 = wx * wy;

    const int o00 = y0 * CUBE_L + x0;
    const int o01 = y0 * CUBE_L + x1;
    const int o10 = y1 * CUBE_L + x0;
    const int o11 = y1 * CUBE_L + x1;

    // Plane k = e*CHANNELS + c lives at x + (18e + 3f + c)*PLANE.
    const float* __restrict__ b = x + (size_t)(3 * f) * PLANE;

    // Depth-3 ring of tap sets; ring index is compile-time (loop unrolled).
    float g[DEPTH][4];

    // Prologue: planes 0 and 1 in flight
    #pragma unroll
    for (int k = 0; k < DEPTH - 1; ++k) {
        const float* bk = b + poff(k);
        g[k][0] = __ldg(bk + o00); g[k][1] = __ldg(bk + o01);
        g[k][2] = __ldg(bk + o10); g[k][3] = __ldg(bk + o11);
    }

    #pragma unroll
    for (int k = 0; k < NPLANES; ++k) {
        // Kick off plane k+2 before consuming plane k.
        if (k + DEPTH - 1 < NPLANES) {
            const int kn = k + DEPTH - 1;
            const float* bn = b + poff(kn);
            float* gn = g[kn % DEPTH];
            gn[0] = __ldg(bn + o00); gn[1] = __ldg(bn + o01);
            gn[2] = __ldg(bn + o10); gn[3] = __ldg(bn + o11);
        }
        const float* gk = g[k % DEPTH];
        const float val = fmaf(gk[0], w00, fmaf(gk[1], w01,
                          fmaf(gk[2], w10, gk[3] * w11)));
        __stcs(out + (size_t)k * NPIX + p, val);
    }
}

extern "C" void kernel_launch(void* const* d_in, const int* in_sizes, int n_in,
                              void* d_out, int out_size)
{
    const float* x        = (const float*)d_in[0];
    const float* uv       = (const float*)d_in[1];
    const int*   face_idx = (const int*)d_in[2];
    float*       out      = (float*)d_out;

    dim3 block(TILE_W * TILE_H);                      // 256 threads
    dim3 grid(EQU_W / TILE_W, EQU_H / TILE_H);        // 64 x 128 = 8192
    cube2equirec_kernel<<<grid, block>>>(x, uv, face_idx, out);
}